// round 13
// baseline (speedup 1.0000x reference)
#include <cuda_runtime.h>
#include <cuda_fp16.h>
#include <cstdint>

#define TOK   2048
#define DIMSZ 1024
#define HID   2048
#define NE    8
#define NSLOT (2 * TOK)

// Scratch (allocation-free: __device__ globals)
__device__ float g_w[NSLOT];
__device__ int   g_cnt[NE];
__device__ int   g_list[NE * TOK];
__device__ __align__(128) __half g_xh[TOK * DIMSZ];
__device__ __align__(128) __half g_wfch[NE * HID * DIMSZ];
__device__ __align__(128) __half g_wph[NE * DIMSZ * HID];
__device__ __align__(128) __half g_h2h[NSLOT * HID];
__device__ float g_y[(size_t)NSLOT * DIMSZ];

// ---------------------------------------------------------------------------
// Helpers
// ---------------------------------------------------------------------------
__device__ __forceinline__ uint32_t smem_u32(const void* p) {
    uint32_t a;
    asm("{ .reg .u64 t; cvta.to.shared.u64 t, %1; cvt.u32.u64 %0, t; }" : "=r"(a) : "l"(p));
    return a;
}
__device__ __forceinline__ void ldm4(uint32_t* r, uint32_t addr) {
    asm volatile("ldmatrix.sync.aligned.m8n8.x4.shared.b16 {%0,%1,%2,%3}, [%4];"
        : "=r"(r[0]), "=r"(r[1]), "=r"(r[2]), "=r"(r[3]) : "r"(addr));
}
__device__ __forceinline__ void mmaf16(float* c, const uint32_t* a, const uint32_t* b) {
    asm volatile(
        "mma.sync.aligned.m16n8k16.row.col.f32.f16.f16.f32 "
        "{%0,%1,%2,%3}, {%4,%5,%6,%7}, {%8,%9}, {%0,%1,%2,%3};"
        : "+f"(c[0]), "+f"(c[1]), "+f"(c[2]), "+f"(c[3])
        : "r"(a[0]), "r"(a[1]), "r"(a[2]), "r"(a[3]), "r"(b[0]), "r"(b[1]));
}
__device__ __forceinline__ void cp16(uint32_t dst, const void* src) {
    asm volatile("cp.async.cg.shared.global [%0], [%1], 16;" :: "r"(dst), "l"(src) : "memory");
}
__device__ __forceinline__ void cp_commit() {
    asm volatile("cp.async.commit_group;" ::: "memory");
}
template<int N> __device__ __forceinline__ void cp_wait() {
    asm volatile("cp.async.wait_group %0;" :: "n"(N) : "memory");
}
// (row, 16B-chunk c in 0..3) -> swizzled byte offset within one 128x64B mat
__device__ __forceinline__ uint32_t swzoff(uint32_t row, uint32_t c) {
    uint32_t q = (((row & 1u) << 2) | c) ^ ((row >> 1) & 7u);
    return ((row >> 1) << 7) + (q << 4);
}

// ---------------------------------------------------------------------------
__global__ void k_zero_counts() {
    if (threadIdx.x < NE) g_cnt[threadIdx.x] = 0;
}

// Convert fp32 -> fp16 for x, Wfc, Wp in ONE launch (flat index)
#define NX4 (TOK * DIMSZ / 4)
#define NF4 (NE * HID * DIMSZ / 4)
__global__ void k_cvt_all(const float4* __restrict__ x, const float4* __restrict__ wfc,
                          const float4* __restrict__ wp) {
    int i = blockIdx.x * 256 + threadIdx.x;
    const float4* s;
    uint2* d;
    int j;
    if (i < NX4)                 { s = x;   d = (uint2*)g_xh;   j = i; }
    else if (i < NX4 + NF4)      { s = wfc; d = (uint2*)g_wfch; j = i - NX4; }
    else if (i < NX4 + 2 * NF4)  { s = wp;  d = (uint2*)g_wph;  j = i - NX4 - NF4; }
    else return;
    float4 v = s[j];
    __half2 h0 = __floats2half2_rn(v.x, v.y);
    __half2 h1 = __floats2half2_rn(v.z, v.w);
    d[j] = make_uint2(*(uint32_t*)&h0, *(uint32_t*)&h1);
}

// Router: one warp per token. logits -> softmax -> top2 -> renormalize (+1e-8)
__global__ void k_router(const float* __restrict__ x, const float* __restrict__ Wr) {
    int warp = threadIdx.x >> 5;
    int lane = threadIdx.x & 31;
    int t = blockIdx.x * 8 + warp;

    float acc[NE];
#pragma unroll
    for (int e = 0; e < NE; ++e) acc[e] = 0.f;

    const float* xr = x + (size_t)t * DIMSZ;
    for (int i = lane; i < DIMSZ; i += 32) {
        float xv = xr[i];
#pragma unroll
        for (int e = 0; e < NE; ++e) acc[e] = fmaf(xv, Wr[e * DIMSZ + i], acc[e]);
    }
#pragma unroll
    for (int e = 0; e < NE; ++e) {
#pragma unroll
        for (int o = 16; o > 0; o >>= 1)
            acc[e] += __shfl_xor_sync(0xffffffffu, acc[e], o);
    }
    if (lane == 0) {
        float m = acc[0];
#pragma unroll
        for (int e = 1; e < NE; ++e) m = fmaxf(m, acc[e]);
        float p[NE]; float Z = 0.f;
#pragma unroll
        for (int e = 0; e < NE; ++e) { p[e] = expf(acc[e] - m); Z += p[e]; }
        float invZ = 1.f / Z;
#pragma unroll
        for (int e = 0; e < NE; ++e) p[e] *= invZ;

        int e0 = 0;
#pragma unroll
        for (int e = 1; e < NE; ++e) if (p[e] > p[e0]) e0 = e;
        int e1 = (e0 == 0) ? 1 : 0;
#pragma unroll
        for (int e = 0; e < NE; ++e) { if (e != e0 && p[e] > p[e1]) e1 = e; }

        float s = p[e0] + p[e1] + 1e-8f;
        g_w[2 * t]     = p[e0] / s;
        g_w[2 * t + 1] = p[e1] / s;
        int q0 = atomicAdd(&g_cnt[e0], 1); g_list[e0 * TOK + q0] = 2 * t;
        int q1 = atomicAdd(&g_cnt[e1], 1); g_list[e1 * TOK + q1] = 2 * t + 1;
    }
}

// ---------------------------------------------------------------------------
// Grouped GEMM: mma.sync m16n8k16 fp16 single-pass, fp32 accumulate.
// CTA = 256 threads (8 warps, 2x4), tile 128x128, warp tile 64x32.
// K-slab = 32 fp16 (64B rows, XOR swizzle). 3-stage cp.async pipeline,
// ONE __syncthreads per slab. Smem per stage: A mat + B mat, 8 KB each.
#define MAT      8192
#define STG      (2 * MAT)            // 16384
#define SLOT_OFF (3 * STG)            // 49152
#define AOFF_OFF (SLOT_OFF + 512)
#define GSMEM    (AOFF_OFF + 512)

template<int KDIM, int NDIM, bool RELU2, int SHIFT, int PHASE>
__global__ void __launch_bounds__(256, 2)
k_gemm_f16() {
    constexpr int NSLAB = KDIM / 32;
    const __half* Ahp = (PHASE == 1) ? g_xh : g_h2h;
    const __half* BA  = (PHASE == 1) ? g_wfch : g_wph;

    int e   = blockIdx.z;
    int cnt = g_cnt[e];
    int m0  = blockIdx.y * 128;
    if (m0 >= cnt) return;
    int n0  = blockIdx.x * 128;
    const __half* B = BA + (size_t)e * NDIM * KDIM;

    extern __shared__ char smem[];
    uint32_t sb = smem_u32(smem);
    int* s_slot = (int*)(smem + SLOT_OFF);
    int* s_aoff = (int*)(smem + AOFF_OFF);
    int tid = threadIdx.x, w = tid >> 5, lane = tid & 31;

    if (tid < 128) {
        int idx = m0 + tid;
        int sl  = g_list[e * TOK + ((idx < cnt) ? idx : m0)];
        s_slot[tid] = (idx < cnt) ? sl : -1;
        s_aoff[tid] = (sl >> SHIFT) * KDIM;
    }
    __syncthreads();

    // Loader: threads 0-127 own A row lrow, threads 128-255 own B row lrow.
    int lrow = tid & 127;
    const __half* srow = (tid < 128) ? (Ahp + s_aoff[lrow])
                                     : (B + (size_t)(n0 + lrow) * KDIM);
    uint32_t dmat = (tid < 128) ? 0u : (uint32_t)MAT;
    uint32_t rbb  = dmat + (((uint32_t)lrow >> 1) << 7);
    uint32_t r7   = ((uint32_t)lrow >> 1) & 7u;
    uint32_t rp   = ((uint32_t)lrow & 1u) << 2;

    // issue one K-slab (32 fp16 per row): 4 cp.async + 1 commit per thread
    auto issue = [&](int ks, int stage) {
        int k0 = ks * 32;
        uint32_t rb = sb + (uint32_t)stage * STG + rbb;
#pragma unroll
        for (int c = 0; c < 4; ++c) {
            uint32_t off = (((rp | (uint32_t)c) ^ r7) << 4);
            cp16(rb + off, srow + k0 + c * 8);
        }
        cp_commit();
    };

    int wy = w >> 2, wx = w & 3;
    // ldmatrix per-lane bases (kk=0); kk=1 via ^0x20
    uint32_t arow0 = (uint32_t)(wy * 64 + (lane & 15));
    uint32_t aB0   = sb + swzoff(arow0, (uint32_t)(lane >> 4));
    uint32_t brow0 = (uint32_t)(wx * 32 + ((lane >> 4) & 1) * 8 + (lane & 7));
    uint32_t bB0   = sb + MAT + swzoff(brow0, (uint32_t)((lane >> 3) & 1));

    float acc[4][4][4];
#pragma unroll
    for (int i = 0; i < 4; ++i)
#pragma unroll
        for (int j = 0; j < 4; ++j)
#pragma unroll
            for (int r = 0; r < 4; ++r) acc[i][j][r] = 0.f;

    issue(0, 0);
    issue(1, 1);
    cp_wait<1>();
    __syncthreads();

#pragma unroll 1
    for (int ks = 0; ks < NSLAB; ++ks) {
        int cur = ks % 3;
        // refill the stage freed at the previous barrier (2 slabs in flight)
        if (ks + 2 < NSLAB) issue(ks + 2, (ks + 2) % 3);
        else                cp_commit();   // empty group keeps wait-count uniform

        uint32_t aS = aB0 + (uint32_t)cur * STG;
        uint32_t bS = bB0 + (uint32_t)cur * STG;
#pragma unroll
        for (int kk = 0; kk < 2; ++kk) {
            uint32_t ah[4][4], bb[2][4];
#pragma unroll
            for (int mt = 0; mt < 4; ++mt)
                ldm4(ah[mt], (aS + mt * 1024) ^ (kk * 0x20));
#pragma unroll
            for (int p = 0; p < 2; ++p)
                ldm4(bb[p], (bS + p * 1024) ^ (kk * 0x20));
#pragma unroll
            for (int mt = 0; mt < 4; ++mt)
#pragma unroll
                for (int nt = 0; nt < 4; ++nt)
                    mmaf16(acc[mt][nt], ah[mt], &bb[nt >> 1][(nt & 1) * 2]);
        }
        cp_wait<1>();      // slab ks+1 landed
        __syncthreads();   // stage cur free for refill next iteration
    }

    // Epilogue
    int rbase = wy * 64 + (lane >> 2);
    int cbase = n0 + wx * 32 + (lane & 3) * 2;
#pragma unroll
    for (int mt = 0; mt < 4; ++mt) {
#pragma unroll
        for (int half = 0; half < 2; ++half) {
            int sl = s_slot[rbase + mt * 16 + half * 8];
            if (sl < 0) continue;
            if (RELU2) {
                uint32_t* oh = (uint32_t*)(g_h2h + (size_t)sl * NDIM + cbase);
#pragma unroll
                for (int nt = 0; nt < 4; ++nt) {
                    float v0 = acc[mt][nt][half * 2 + 0];
                    float v1 = acc[mt][nt][half * 2 + 1];
                    v0 = fmaxf(v0, 0.f); v0 *= v0;
                    v1 = fmaxf(v1, 0.f); v1 *= v1;
                    __half2 hp = __floats2half2_rn(v0, v1);
                    oh[nt * 4] = *(uint32_t*)&hp;
                }
            } else {
                float* oy = g_y + (size_t)sl * NDIM + cbase;
#pragma unroll
                for (int nt = 0; nt < 4; ++nt) {
                    *(float2*)(oy + nt * 8) =
                        make_float2(acc[mt][nt][half * 2 + 0], acc[mt][nt][half * 2 + 1]);
                }
            }
        }
    }
}

// ---------------------------------------------------------------------------
__global__ void k_combine(float* __restrict__ out, int out_size) {
    int t = blockIdx.x;
    int i = threadIdx.x;
    float w0 = g_w[2 * t];
    float w1 = g_w[2 * t + 1];
    float4 a = ((const float4*)(g_y + (size_t)(2 * t) * DIMSZ))[i];
    float4 b = ((const float4*)(g_y + (size_t)(2 * t + 1) * DIMSZ))[i];
    float4 r;
    r.x = w0 * a.x + w1 * b.x;
    r.y = w0 * a.y + w1 * b.y;
    r.z = w0 * a.z + w1 * b.z;
    r.w = w0 * a.w + w1 * b.w;
    ((float4*)(out + (size_t)t * DIMSZ))[i] = r;
    if (t == 0 && i == 0) {
        for (int j = TOK * DIMSZ; j < out_size; ++j) out[j] = 0.f;  // aux_loss tail
    }
}

// ---------------------------------------------------------------------------
extern "C" void kernel_launch(void* const* d_in, const int* in_sizes, int n_in,
                              void* d_out, int out_size) {
    const float* x   = (const float*)d_in[0];   // [1, 2048, 1024]
    const float* Wr  = (const float*)d_in[1];   // [8, 1024]
    const float* Wfc = (const float*)d_in[2];   // [8, 2048, 1024]
    const float* Wp  = (const float*)d_in[3];   // [8, 1024, 2048]
    float* out = (float*)d_out;

    cudaFuncSetAttribute(k_gemm_f16<DIMSZ, HID, true, 1, 1>,
                         cudaFuncAttributeMaxDynamicSharedMemorySize, GSMEM);
    cudaFuncSetAttribute(k_gemm_f16<HID, DIMSZ, false, 0, 2>,
                         cudaFuncAttributeMaxDynamicSharedMemorySize, GSMEM);

    k_zero_counts<<<1, 32>>>();
    k_router<<<TOK / 8, 256>>>(x, Wr);
    k_cvt_all<<<(NX4 + 2 * NF4 + 255) / 256, 256>>>(
        (const float4*)x, (const float4*)Wfc, (const float4*)Wp);
    // GEMM1: h2[slot, H] = relu(x[tok] @ Wfc[e]^T)^2  (fp16 output)
    k_gemm_f16<DIMSZ, HID, true, 1, 1>
        <<<dim3(HID / 128, TOK / 128, NE), 256, GSMEM>>>();
    // GEMM2: y[slot, D] = h2[slot] @ Wp[e]^T
    k_gemm_f16<HID, DIMSZ, false, 0, 2>
        <<<dim3(DIMSZ / 128, TOK / 128, NE), 256, GSMEM>>>();
    k_combine<<<TOK, 256>>>(out, out_size);
}

// round 14
// speedup vs baseline: 1.7995x; 1.7995x over previous
#include <cuda_runtime.h>
#include <cuda_fp16.h>
#include <cstdint>

#define TOK   2048
#define DIMSZ 1024
#define HID   2048
#define NE    8
#define NSLOT (2 * TOK)

// Scratch (allocation-free: __device__ globals)
__device__ float g_w[NSLOT];
__device__ int   g_cnt[NE];
__device__ int   g_list[NE * TOK];
__device__ __align__(128) __half g_xh[TOK * DIMSZ];
__device__ __align__(128) __half g_wfch[NE * HID * DIMSZ];
__device__ __align__(128) __half g_wph[NE * DIMSZ * HID];
__device__ __align__(128) __half g_h2h[NSLOT * HID];

// ---------------------------------------------------------------------------
// Helpers
// ---------------------------------------------------------------------------
__device__ __forceinline__ uint32_t smem_u32(const void* p) {
    uint32_t a;
    asm("{ .reg .u64 t; cvta.to.shared.u64 t, %1; cvt.u32.u64 %0, t; }" : "=r"(a) : "l"(p));
    return a;
}
__device__ __forceinline__ void ldm4(uint32_t* r, uint32_t addr) {
    asm volatile("ldmatrix.sync.aligned.m8n8.x4.shared.b16 {%0,%1,%2,%3}, [%4];"
        : "=r"(r[0]), "=r"(r[1]), "=r"(r[2]), "=r"(r[3]) : "r"(addr));
}
__device__ __forceinline__ void mmaf16(float* c, const uint32_t* a, const uint32_t* b) {
    asm volatile(
        "mma.sync.aligned.m16n8k16.row.col.f32.f16.f16.f32 "
        "{%0,%1,%2,%3}, {%4,%5,%6,%7}, {%8,%9}, {%0,%1,%2,%3};"
        : "+f"(c[0]), "+f"(c[1]), "+f"(c[2]), "+f"(c[3])
        : "r"(a[0]), "r"(a[1]), "r"(a[2]), "r"(a[3]), "r"(b[0]), "r"(b[1]));
}
__device__ __forceinline__ void cp16(uint32_t dst, const void* src) {
    asm volatile("cp.async.cg.shared.global [%0], [%1], 16;" :: "r"(dst), "l"(src) : "memory");
}
__device__ __forceinline__ void cp_commit() {
    asm volatile("cp.async.commit_group;" ::: "memory");
}
template<int N> __device__ __forceinline__ void cp_wait() {
    asm volatile("cp.async.wait_group %0;" :: "n"(N) : "memory");
}
// (row, 16B-chunk c in 0..3) -> swizzled byte offset within one 128x64B mat
__device__ __forceinline__ uint32_t swzoff(uint32_t row, uint32_t c) {
    uint32_t q = (((row & 1u) << 2) | c) ^ ((row >> 1) & 7u);
    return ((row >> 1) << 7) + (q << 4);
}

#define NX4 (TOK * DIMSZ / 4)
#define NF4 (NE * HID * DIMSZ / 4)

// ---------------------------------------------------------------------------
// Zero expert counters + zero the output buffer (graph replays re-zero)
__global__ void k_zero(float* __restrict__ out, int out_size) {
    int i = blockIdx.x * 256 + threadIdx.x;
    if (blockIdx.x == 0 && threadIdx.x < NE) g_cnt[threadIdx.x] = 0;
    int n4 = out_size >> 2;
    if (i < n4) ((float4*)out)[i] = make_float4(0.f, 0.f, 0.f, 0.f);
    if (i == 0) {
        for (int j = n4 << 2; j < out_size; ++j) out[j] = 0.f;
    }
}

// Convert Wfc fp32 -> fp16 (x handled by router; Wp handled inside GEMM1)
__global__ void k_cvt_wfc(const float4* __restrict__ wfc) {
    int i = blockIdx.x * 256 + threadIdx.x;
    if (i >= NF4) return;
    float4 v = wfc[i];
    __half2 h0 = __floats2half2_rn(v.x, v.y);
    __half2 h1 = __floats2half2_rn(v.z, v.w);
    ((uint2*)g_wfch)[i] = make_uint2(*(uint32_t*)&h0, *(uint32_t*)&h1);
}

// Router: one warp per token. logits -> softmax -> top2 -> renormalize (+1e-8)
// Also converts this token's x row to fp16 (g_xh).
__global__ void k_router(const float* __restrict__ x, const float* __restrict__ Wr) {
    int warp = threadIdx.x >> 5;
    int lane = threadIdx.x & 31;
    int t = blockIdx.x * 8 + warp;

    float acc[NE];
#pragma unroll
    for (int e = 0; e < NE; ++e) acc[e] = 0.f;

    const float* xr = x + (size_t)t * DIMSZ;
    for (int i = lane; i < DIMSZ; i += 32) {
        float xv = xr[i];
#pragma unroll
        for (int e = 0; e < NE; ++e) acc[e] = fmaf(xv, Wr[e * DIMSZ + i], acc[e]);
    }
    // fp16 conversion of the row (reads L2-hot data)
    {
        uint32_t* dst = (uint32_t*)(g_xh + (size_t)t * DIMSZ);
        const float2* src = (const float2*)xr;
#pragma unroll
        for (int i = lane; i < DIMSZ / 2; i += 32) {
            float2 v = src[i];
            __half2 h = __floats2half2_rn(v.x, v.y);
            dst[i] = *(uint32_t*)&h;
        }
    }
#pragma unroll
    for (int e = 0; e < NE; ++e) {
#pragma unroll
        for (int o = 16; o > 0; o >>= 1)
            acc[e] += __shfl_xor_sync(0xffffffffu, acc[e], o);
    }
    if (lane == 0) {
        float m = acc[0];
#pragma unroll
        for (int e = 1; e < NE; ++e) m = fmaxf(m, acc[e]);
        float p[NE]; float Z = 0.f;
#pragma unroll
        for (int e = 0; e < NE; ++e) { p[e] = expf(acc[e] - m); Z += p[e]; }
        float invZ = 1.f / Z;
#pragma unroll
        for (int e = 0; e < NE; ++e) p[e] *= invZ;

        int e0 = 0;
#pragma unroll
        for (int e = 1; e < NE; ++e) if (p[e] > p[e0]) e0 = e;
        int e1 = (e0 == 0) ? 1 : 0;
#pragma unroll
        for (int e = 0; e < NE; ++e) { if (e != e0 && p[e] > p[e1]) e1 = e; }

        float s = p[e0] + p[e1] + 1e-8f;
        g_w[2 * t]     = p[e0] / s;
        g_w[2 * t + 1] = p[e1] / s;
        int q0 = atomicAdd(&g_cnt[e0], 1); g_list[e0 * TOK + q0] = 2 * t;
        int q1 = atomicAdd(&g_cnt[e1], 1); g_list[e1 * TOK + q1] = 2 * t + 1;
    }
}

// ---------------------------------------------------------------------------
// Grouped GEMM: mma.sync m16n8k16 fp16 single-pass, fp32 accumulate.
// CTA = 128 threads (4 warps 2x2), tile 128x128, warp tile 64x64.
// K-slab = 32 fp16 (64B rows, XOR swizzle). 3-stage cp.async pipeline,
// ONE __syncthreads per slab.  (R11 core — do not touch.)
// PHASE 1 extra: blockIdx.z == NE plane converts Wp fp32->fp16 (overlapped).
// PHASE 2: epilogue scatters w*v into out via atomicAdd (combine fused).
#define MAT      8192
#define STG      (2 * MAT)            // 16384
#define SLOT_OFF (3 * STG)            // 49152
#define AOFF_OFF (SLOT_OFF + 512)
#define GSMEM    (AOFF_OFF + 512)

template<int KDIM, int NDIM, bool RELU2, int SHIFT, int PHASE>
__global__ void __launch_bounds__(128, 2)
k_gemm_f16(const float4* __restrict__ wp_src, float* __restrict__ out) {
    constexpr int NSLAB = KDIM / 32;

    if (PHASE == 1 && blockIdx.z == NE) {
        // Wp conversion plane: 256 CTAs x 128 threads, overlapped with GEMM1
        int flat = (blockIdx.y * 16 + blockIdx.x) * 128 + threadIdx.x;
#pragma unroll 4
        for (int j = 0; j < NF4 / 32768; ++j) {
            int i = flat + j * 32768;
            float4 v = wp_src[i];
            __half2 h0 = __floats2half2_rn(v.x, v.y);
            __half2 h1 = __floats2half2_rn(v.z, v.w);
            ((uint2*)g_wph)[i] = make_uint2(*(uint32_t*)&h0, *(uint32_t*)&h1);
        }
        return;
    }

    const __half* Ahp = (PHASE == 1) ? g_xh : g_h2h;
    const __half* BA  = (PHASE == 1) ? g_wfch : g_wph;

    int e   = blockIdx.z;
    int cnt = g_cnt[e];
    int m0  = blockIdx.y * 128;
    if (m0 >= cnt) return;
    int n0  = blockIdx.x * 128;
    const __half* B = BA + (size_t)e * NDIM * KDIM;

    extern __shared__ char smem[];
    uint32_t sb = smem_u32(smem);
    int* s_slot = (int*)(smem + SLOT_OFF);
    int* s_aoff = (int*)(smem + AOFF_OFF);
    int tid = threadIdx.x, w = tid >> 5, lane = tid & 31;

    {
        int idx = m0 + tid;
        int sl  = g_list[e * TOK + ((idx < cnt) ? idx : m0)];
        s_slot[tid] = (idx < cnt) ? sl : -1;
        s_aoff[tid] = (sl >> SHIFT) * KDIM;
    }
    __syncthreads();

    int lrow = lane & 7, lchunk = lane >> 3;
    int raoff[4];
    size_t boff[4];
#pragma unroll
    for (int j = 0; j < 4; ++j) {
        int row = (4 * j + w) * 8 + lrow;
        raoff[j] = s_aoff[row] + lchunk * 8;
        boff[j]  = (size_t)(n0 + row) * KDIM + lchunk * 8;
    }

    // issue one K-slab (32 fp16 per row): 8 cp.async + 1 commit
    auto issue = [&](int ks, int stage) {
        int k0 = ks * 32;
        uint32_t stg = sb + (uint32_t)stage * STG;
#pragma unroll
        for (int j = 0; j < 4; ++j) {
            uint32_t row = (uint32_t)(4 * j + w) * 8 + lrow;
            uint32_t so = stg + swzoff(row, lchunk);
            cp16(so,       Ahp + raoff[j] + k0);
            cp16(so + MAT, B + boff[j] + k0);
        }
        cp_commit();
    };

    int wy = w >> 1, wx = w & 1;
    // ldmatrix per-lane bases (kk=0); kk=1 via ^0x20
    uint32_t aQ = (((lane & 1u) << 2) | (uint32_t)(lane >> 4)) ^ (((uint32_t)(lane & 15) >> 1) & 7u);
    uint32_t aB0 = sb + (uint32_t)((wy * 64 + (lane & 15)) >> 1) * 128 + aQ * 16;
    uint32_t brow = (uint32_t)(wx * 64 + ((lane >> 4) & 1) * 8 + (lane & 7));
    uint32_t bc   = (uint32_t)((lane >> 3) & 1);
    uint32_t bQ   = (((brow & 1u) << 2) | bc) ^ ((brow >> 1) & 7u);
    uint32_t bB0  = sb + MAT + (brow >> 1) * 128 + bQ * 16;

    float acc[4][8][4];
#pragma unroll
    for (int i = 0; i < 4; ++i)
#pragma unroll
        for (int j = 0; j < 8; ++j)
#pragma unroll
            for (int r = 0; r < 4; ++r) acc[i][j][r] = 0.f;

    issue(0, 0);
    issue(1, 1);
    cp_wait<1>();
    __syncthreads();

#pragma unroll 1
    for (int ks = 0; ks < NSLAB; ++ks) {
        int cur = ks % 3;
        if (ks + 2 < NSLAB) issue(ks + 2, (ks + 2) % 3);
        else                cp_commit();   // empty group keeps wait-count uniform

        uint32_t aS = aB0 + (uint32_t)cur * STG;
        uint32_t bS = bB0 + (uint32_t)cur * STG;
#pragma unroll
        for (int kk = 0; kk < 2; ++kk) {
            uint32_t ah[4][4], bb[4][4];
#pragma unroll
            for (int mt = 0; mt < 4; ++mt)
                ldm4(ah[mt], (aS + mt * 1024) ^ (kk * 0x20));
#pragma unroll
            for (int p = 0; p < 4; ++p)
                ldm4(bb[p], (bS + p * 1024) ^ (kk * 0x20));
#pragma unroll
            for (int mt = 0; mt < 4; ++mt)
#pragma unroll
                for (int nt = 0; nt < 8; ++nt)
                    mmaf16(acc[mt][nt], ah[mt], &bb[nt >> 1][(nt & 1) * 2]);
        }
        cp_wait<1>();      // slab ks+1 landed
        __syncthreads();   // stage cur free for refill next iteration
    }

    // Epilogue
    int rbase = wy * 64 + (lane >> 2);
    int cbase = n0 + wx * 64 + (lane & 3) * 2;
#pragma unroll
    for (int mt = 0; mt < 4; ++mt) {
#pragma unroll
        for (int half = 0; half < 2; ++half) {
            int sl = s_slot[rbase + mt * 16 + half * 8];
            if (sl < 0) continue;
            if (RELU2) {
                uint32_t* oh = (uint32_t*)(g_h2h + (size_t)sl * NDIM + cbase);
#pragma unroll
                for (int nt = 0; nt < 8; ++nt) {
                    float v0 = acc[mt][nt][half * 2 + 0];
                    float v1 = acc[mt][nt][half * 2 + 1];
                    v0 = fmaxf(v0, 0.f); v0 *= v0;
                    v1 = fmaxf(v1, 0.f); v1 *= v1;
                    __half2 hp = __floats2half2_rn(v0, v1);
                    oh[nt * 4] = *(uint32_t*)&hp;
                }
            } else {
                // fused combine: out[token] += w[slot] * v   (2 contributions
                // per element; fp add of two terms is order-exact)
                float wgt = g_w[sl];
                float* orow = out + (size_t)(sl >> 1) * DIMSZ + cbase;
#pragma unroll
                for (int nt = 0; nt < 8; ++nt) {
                    atomicAdd(&orow[nt * 8],     wgt * acc[mt][nt][half * 2 + 0]);
                    atomicAdd(&orow[nt * 8 + 1], wgt * acc[mt][nt][half * 2 + 1]);
                }
            }
        }
    }
}

// ---------------------------------------------------------------------------
extern "C" void kernel_launch(void* const* d_in, const int* in_sizes, int n_in,
                              void* d_out, int out_size) {
    const float* x   = (const float*)d_in[0];   // [1, 2048, 1024]
    const float* Wr  = (const float*)d_in[1];   // [8, 1024]
    const float* Wfc = (const float*)d_in[2];   // [8, 2048, 1024]
    const float* Wp  = (const float*)d_in[3];   // [8, 1024, 2048]
    float* out = (float*)d_out;

    cudaFuncSetAttribute(k_gemm_f16<DIMSZ, HID, true, 1, 1>,
                         cudaFuncAttributeMaxDynamicSharedMemorySize, GSMEM);
    cudaFuncSetAttribute(k_gemm_f16<HID, DIMSZ, false, 0, 2>,
                         cudaFuncAttributeMaxDynamicSharedMemorySize, GSMEM);

    k_zero<<<(out_size / 4 + 255) / 256, 256>>>(out, out_size);
    k_router<<<TOK / 8, 256>>>(x, Wr);
    k_cvt_wfc<<<(NF4 + 255) / 256, 256>>>((const float4*)Wfc);
    // GEMM1: h2 = relu(x @ Wfc^T)^2 (fp16 out); z==NE plane converts Wp
    k_gemm_f16<DIMSZ, HID, true, 1, 1>
        <<<dim3(HID / 128, TOK / 128, NE + 1), 128, GSMEM>>>((const float4*)Wp, nullptr);
    // GEMM2: out[token] += w[slot] * (h2[slot] @ Wp[e]^T)  (combine fused)
    k_gemm_f16<HID, DIMSZ, false, 0, 2>
        <<<dim3(DIMSZ / 128, TOK / 128, NE), 128, GSMEM>>>(nullptr, out);
}

// round 15
// speedup vs baseline: 1.8217x; 1.0123x over previous
#include <cuda_runtime.h>
#include <cuda_fp16.h>
#include <cstdint>

#define TOK   2048
#define DIMSZ 1024
#define HID   2048
#define NE    8
#define NSLOT (2 * TOK)

// Scratch (allocation-free: __device__ globals)
__device__ float g_w[NSLOT];
__device__ int   g_cnt[NE];
__device__ int   g_list[NE * TOK];
__device__ __align__(128) __half g_xh[TOK * DIMSZ];
__device__ __align__(128) __half g_wfch[NE * HID * DIMSZ];
__device__ __align__(128) __half g_wph[NE * DIMSZ * HID];
__device__ __align__(128) __half g_h2h[NSLOT * HID];

// ---------------------------------------------------------------------------
// Helpers
// ---------------------------------------------------------------------------
__device__ __forceinline__ uint32_t smem_u32(const void* p) {
    uint32_t a;
    asm("{ .reg .u64 t; cvta.to.shared.u64 t, %1; cvt.u32.u64 %0, t; }" : "=r"(a) : "l"(p));
    return a;
}
__device__ __forceinline__ void ldm4(uint32_t* r, uint32_t addr) {
    asm volatile("ldmatrix.sync.aligned.m8n8.x4.shared.b16 {%0,%1,%2,%3}, [%4];"
        : "=r"(r[0]), "=r"(r[1]), "=r"(r[2]), "=r"(r[3]) : "r"(addr));
}
__device__ __forceinline__ void mmaf16(float* c, const uint32_t* a, const uint32_t* b) {
    asm volatile(
        "mma.sync.aligned.m16n8k16.row.col.f32.f16.f16.f32 "
        "{%0,%1,%2,%3}, {%4,%5,%6,%7}, {%8,%9}, {%0,%1,%2,%3};"
        : "+f"(c[0]), "+f"(c[1]), "+f"(c[2]), "+f"(c[3])
        : "r"(a[0]), "r"(a[1]), "r"(a[2]), "r"(a[3]), "r"(b[0]), "r"(b[1]));
}
__device__ __forceinline__ void cp16(uint32_t dst, const void* src) {
    asm volatile("cp.async.cg.shared.global [%0], [%1], 16;" :: "r"(dst), "l"(src) : "memory");
}
__device__ __forceinline__ void cp_commit() {
    asm volatile("cp.async.commit_group;" ::: "memory");
}
template<int N> __device__ __forceinline__ void cp_wait() {
    asm volatile("cp.async.wait_group %0;" :: "n"(N) : "memory");
}
// (row, 16B-chunk c in 0..3) -> swizzled byte offset within one 128x64B mat
__device__ __forceinline__ uint32_t swzoff(uint32_t row, uint32_t c) {
    uint32_t q = (((row & 1u) << 2) | c) ^ ((row >> 1) & 7u);
    return ((row >> 1) << 7) + (q << 4);
}

#define NX4 (TOK * DIMSZ / 4)
#define NF4 (NE * HID * DIMSZ / 4)     // 4194304
#define NB_CVT (NF4 / 256)             // 16384 blocks
#define NB_RTR (TOK / 8)               // 256 blocks

// ---------------------------------------------------------------------------
__global__ void k_zero_counts() {
    if (threadIdx.x < NE) g_cnt[threadIdx.x] = 0;
}

// Fused front: [0,NB_CVT) cvt Wfc->fp16 | [NB_CVT,+NB_RTR) router+x cvt |
// rest: zero out. All three are mutually independent.
__global__ void k_front(const float* __restrict__ x, const float* __restrict__ Wr,
                        const float4* __restrict__ wfc,
                        float* __restrict__ out, int out_size) {
    int b = blockIdx.x;
    if (b < NB_CVT) {
        int i = b * 256 + threadIdx.x;
        float4 v = wfc[i];
        __half2 h0 = __floats2half2_rn(v.x, v.y);
        __half2 h1 = __floats2half2_rn(v.z, v.w);
        ((uint2*)g_wfch)[i] = make_uint2(*(uint32_t*)&h0, *(uint32_t*)&h1);
        return;
    }
    if (b >= NB_CVT + NB_RTR) {
        // zero the output buffer (GEMM2 accumulates atomically)
        int i = (b - NB_CVT - NB_RTR) * 256 + threadIdx.x;
        int n4 = out_size >> 2;
        if (i < n4) ((float4*)out)[i] = make_float4(0.f, 0.f, 0.f, 0.f);
        if (i == 0) {
            for (int j = n4 << 2; j < out_size; ++j) out[j] = 0.f;
        }
        return;
    }
    // Router: one warp per token; also converts this token's x row to fp16.
    int warp = threadIdx.x >> 5;
    int lane = threadIdx.x & 31;
    int t = (b - NB_CVT) * 8 + warp;

    float acc[NE];
#pragma unroll
    for (int e = 0; e < NE; ++e) acc[e] = 0.f;

    const float* xr = x + (size_t)t * DIMSZ;
    for (int i = lane; i < DIMSZ; i += 32) {
        float xv = xr[i];
#pragma unroll
        for (int e = 0; e < NE; ++e) acc[e] = fmaf(xv, Wr[e * DIMSZ + i], acc[e]);
    }
    {
        uint32_t* dst = (uint32_t*)(g_xh + (size_t)t * DIMSZ);
        const float2* src = (const float2*)xr;
#pragma unroll
        for (int i = lane; i < DIMSZ / 2; i += 32) {
            float2 v = src[i];
            __half2 h = __floats2half2_rn(v.x, v.y);
            dst[i] = *(uint32_t*)&h;
        }
    }
#pragma unroll
    for (int e = 0; e < NE; ++e) {
#pragma unroll
        for (int o = 16; o > 0; o >>= 1)
            acc[e] += __shfl_xor_sync(0xffffffffu, acc[e], o);
    }
    if (lane == 0) {
        float m = acc[0];
#pragma unroll
        for (int e = 1; e < NE; ++e) m = fmaxf(m, acc[e]);
        float p[NE]; float Z = 0.f;
#pragma unroll
        for (int e = 0; e < NE; ++e) { p[e] = expf(acc[e] - m); Z += p[e]; }
        float invZ = 1.f / Z;
#pragma unroll
        for (int e = 0; e < NE; ++e) p[e] *= invZ;

        int e0 = 0;
#pragma unroll
        for (int e = 1; e < NE; ++e) if (p[e] > p[e0]) e0 = e;
        int e1 = (e0 == 0) ? 1 : 0;
#pragma unroll
        for (int e = 0; e < NE; ++e) { if (e != e0 && p[e] > p[e1]) e1 = e; }

        float s = p[e0] + p[e1] + 1e-8f;
        g_w[2 * t]     = p[e0] / s;
        g_w[2 * t + 1] = p[e1] / s;
        int q0 = atomicAdd(&g_cnt[e0], 1); g_list[e0 * TOK + q0] = 2 * t;
        int q1 = atomicAdd(&g_cnt[e1], 1); g_list[e1 * TOK + q1] = 2 * t + 1;
    }
}

// ---------------------------------------------------------------------------
// Grouped GEMM: mma.sync m16n8k16 fp16 single-pass, fp32 accumulate.
// CTA = 128 threads (4 warps 2x2), tile 128x128, warp tile 64x64.
// K-slab = 32 fp16 (64B rows, XOR swizzle). 3-stage cp.async pipeline,
// ONE __syncthreads per slab.  (R11 core — frozen.)
// PHASE 1 extra: blockIdx.z == NE plane converts Wp fp32->fp16 (overlapped).
// PHASE 2: epilogue scatters w*v into out via atomicAdd (combine fused).
#define MAT      8192
#define STG      (2 * MAT)            // 16384
#define SLOT_OFF (3 * STG)            // 49152
#define AOFF_OFF (SLOT_OFF + 512)
#define GSMEM    (AOFF_OFF + 512)

template<int KDIM, int NDIM, bool RELU2, int SHIFT, int PHASE>
__global__ void __launch_bounds__(128, 2)
k_gemm_f16(const float4* __restrict__ wp_src, float* __restrict__ out) {
    constexpr int NSLAB = KDIM / 32;

    if (PHASE == 1 && blockIdx.z == NE) {
        // Wp conversion plane: 256 CTAs x 128 threads, overlapped with GEMM1
        int flat = (blockIdx.y * 16 + blockIdx.x) * 128 + threadIdx.x;
#pragma unroll 4
        for (int j = 0; j < NF4 / 32768; ++j) {
            int i = flat + j * 32768;
            float4 v = wp_src[i];
            __half2 h0 = __floats2half2_rn(v.x, v.y);
            __half2 h1 = __floats2half2_rn(v.z, v.w);
            ((uint2*)g_wph)[i] = make_uint2(*(uint32_t*)&h0, *(uint32_t*)&h1);
        }
        return;
    }

    const __half* Ahp = (PHASE == 1) ? g_xh : g_h2h;
    const __half* BA  = (PHASE == 1) ? g_wfch : g_wph;

    int e   = blockIdx.z;
    int cnt = g_cnt[e];
    int m0  = blockIdx.y * 128;
    if (m0 >= cnt) return;
    int n0  = blockIdx.x * 128;
    const __half* B = BA + (size_t)e * NDIM * KDIM;

    extern __shared__ char smem[];
    uint32_t sb = smem_u32(smem);
    int* s_slot = (int*)(smem + SLOT_OFF);
    int* s_aoff = (int*)(smem + AOFF_OFF);
    int tid = threadIdx.x, w = tid >> 5, lane = tid & 31;

    {
        int idx = m0 + tid;
        int sl  = g_list[e * TOK + ((idx < cnt) ? idx : m0)];
        s_slot[tid] = (idx < cnt) ? sl : -1;
        s_aoff[tid] = (sl >> SHIFT) * KDIM;
    }
    __syncthreads();

    int lrow = lane & 7, lchunk = lane >> 3;
    int raoff[4];
    size_t boff[4];
#pragma unroll
    for (int j = 0; j < 4; ++j) {
        int row = (4 * j + w) * 8 + lrow;
        raoff[j] = s_aoff[row] + lchunk * 8;
        boff[j]  = (size_t)(n0 + row) * KDIM + lchunk * 8;
    }

    // issue one K-slab (32 fp16 per row): 8 cp.async + 1 commit
    auto issue = [&](int ks, int stage) {
        int k0 = ks * 32;
        uint32_t stg = sb + (uint32_t)stage * STG;
#pragma unroll
        for (int j = 0; j < 4; ++j) {
            uint32_t row = (uint32_t)(4 * j + w) * 8 + lrow;
            uint32_t so = stg + swzoff(row, lchunk);
            cp16(so,       Ahp + raoff[j] + k0);
            cp16(so + MAT, B + boff[j] + k0);
        }
        cp_commit();
    };

    int wy = w >> 1, wx = w & 1;
    // ldmatrix per-lane bases (kk=0); kk=1 via ^0x20
    uint32_t aQ = (((lane & 1u) << 2) | (uint32_t)(lane >> 4)) ^ (((uint32_t)(lane & 15) >> 1) & 7u);
    uint32_t aB0 = sb + (uint32_t)((wy * 64 + (lane & 15)) >> 1) * 128 + aQ * 16;
    uint32_t brow = (uint32_t)(wx * 64 + ((lane >> 4) & 1) * 8 + (lane & 7));
    uint32_t bc   = (uint32_t)((lane >> 3) & 1);
    uint32_t bQ   = (((brow & 1u) << 2) | bc) ^ ((brow >> 1) & 7u);
    uint32_t bB0  = sb + MAT + (brow >> 1) * 128 + bQ * 16;

    float acc[4][8][4];
#pragma unroll
    for (int i = 0; i < 4; ++i)
#pragma unroll
        for (int j = 0; j < 8; ++j)
#pragma unroll
            for (int r = 0; r < 4; ++r) acc[i][j][r] = 0.f;

    issue(0, 0);
    issue(1, 1);
    cp_wait<1>();
    __syncthreads();

#pragma unroll 1
    for (int ks = 0; ks < NSLAB; ++ks) {
        int cur = ks % 3;
        if (ks + 2 < NSLAB) issue(ks + 2, (ks + 2) % 3);
        else                cp_commit();   // empty group keeps wait-count uniform

        uint32_t aS = aB0 + (uint32_t)cur * STG;
        uint32_t bS = bB0 + (uint32_t)cur * STG;
#pragma unroll
        for (int kk = 0; kk < 2; ++kk) {
            uint32_t ah[4][4], bb[4][4];
#pragma unroll
            for (int mt = 0; mt < 4; ++mt)
                ldm4(ah[mt], (aS + mt * 1024) ^ (kk * 0x20));
#pragma unroll
            for (int p = 0; p < 4; ++p)
                ldm4(bb[p], (bS + p * 1024) ^ (kk * 0x20));
#pragma unroll
            for (int mt = 0; mt < 4; ++mt)
#pragma unroll
                for (int nt = 0; nt < 8; ++nt)
                    mmaf16(acc[mt][nt], ah[mt], &bb[nt >> 1][(nt & 1) * 2]);
        }
        cp_wait<1>();      // slab ks+1 landed
        __syncthreads();   // stage cur free for refill next iteration
    }

    // Epilogue
    int rbase = wy * 64 + (lane >> 2);
    int cbase = n0 + wx * 64 + (lane & 3) * 2;
#pragma unroll
    for (int mt = 0; mt < 4; ++mt) {
#pragma unroll
        for (int half = 0; half < 2; ++half) {
            int sl = s_slot[rbase + mt * 16 + half * 8];
            if (sl < 0) continue;
            if (RELU2) {
                uint32_t* oh = (uint32_t*)(g_h2h + (size_t)sl * NDIM + cbase);
#pragma unroll
                for (int nt = 0; nt < 8; ++nt) {
                    float v0 = acc[mt][nt][half * 2 + 0];
                    float v1 = acc[mt][nt][half * 2 + 1];
                    v0 = fmaxf(v0, 0.f); v0 *= v0;
                    v1 = fmaxf(v1, 0.f); v1 *= v1;
                    __half2 hp = __floats2half2_rn(v0, v1);
                    oh[nt * 4] = *(uint32_t*)&hp;
                }
            } else {
                // fused combine: out[token] += w[slot] * v   (2 contributions
                // per element; fp add of two terms is order-exact)
                float wgt = g_w[sl];
                float* orow = out + (size_t)(sl >> 1) * DIMSZ + cbase;
#pragma unroll
                for (int nt = 0; nt < 8; ++nt) {
                    atomicAdd(&orow[nt * 8],     wgt * acc[mt][nt][half * 2 + 0]);
                    atomicAdd(&orow[nt * 8 + 1], wgt * acc[mt][nt][half * 2 + 1]);
                }
            }
        }
    }
}

// ---------------------------------------------------------------------------
extern "C" void kernel_launch(void* const* d_in, const int* in_sizes, int n_in,
                              void* d_out, int out_size) {
    const float* x   = (const float*)d_in[0];   // [1, 2048, 1024]
    const float* Wr  = (const float*)d_in[1];   // [8, 1024]
    const float* Wfc = (const float*)d_in[2];   // [8, 2048, 1024]
    const float* Wp  = (const float*)d_in[3];   // [8, 1024, 2048]
    float* out = (float*)d_out;

    cudaFuncSetAttribute(k_gemm_f16<DIMSZ, HID, true, 1, 1>,
                         cudaFuncAttributeMaxDynamicSharedMemorySize, GSMEM);
    cudaFuncSetAttribute(k_gemm_f16<HID, DIMSZ, false, 0, 2>,
                         cudaFuncAttributeMaxDynamicSharedMemorySize, GSMEM);

    int nb_zero = (out_size / 4 + 255) / 256 + 1;
    k_zero_counts<<<1, 32>>>();
    k_front<<<NB_CVT + NB_RTR + nb_zero, 256>>>(x, Wr, (const float4*)Wfc, out, out_size);
    // GEMM1: h2 = relu(x @ Wfc^T)^2 (fp16 out); z==NE plane converts Wp
    k_gemm_f16<DIMSZ, HID, true, 1, 1>
        <<<dim3(HID / 128, TOK / 128, NE + 1), 128, GSMEM>>>((const float4*)Wp, nullptr);
    // GEMM2: out[token] += w[slot] * (h2[slot] @ Wp[e]^T)  (combine fused)
    k_gemm_f16<HID, DIMSZ, false, 0, 2>
        <<<dim3(DIMSZ / 128, TOK / 128, NE), 128, GSMEM>>>(nullptr, out);
}